// round 13
// baseline (speedup 1.0000x reference)
#include <cuda_runtime.h>
#include <cuda_bf16.h>
#include <math.h>
#include <stdint.h>

#define D_DIM 768
#define H_DIM 1024
#define E_NUM 8
#define B_MAX 8192
#define NSLOT (2 * B_MAX)

// ---------------- scratch (device globals; no allocations) ----------------
__device__ int   g_counts[E_NUM];
__device__ int   g_base[E_NUM + 1];
__device__ int   g_tok [E_NUM * B_MAX];
__device__ float g_gate[E_NUM * B_MAX];
__device__ float g_hbuf[(size_t)NSLOT * H_DIM];   // fp32 h (pre-LN)
// pre-split bf16 hi/lo operands
__device__ __nv_bfloat16 g_xs_hi[(size_t)B_MAX * D_DIM];
__device__ __nv_bfloat16 g_xs_lo[(size_t)B_MAX * D_DIM];
__device__ __nv_bfloat16 g_w1_hi[(size_t)E_NUM * D_DIM * H_DIM];
__device__ __nv_bfloat16 g_w1_lo[(size_t)E_NUM * D_DIM * H_DIM];
__device__ __nv_bfloat16 g_w2_hi[(size_t)E_NUM * H_DIM * D_DIM];
__device__ __nv_bfloat16 g_w2_lo[(size_t)E_NUM * H_DIM * D_DIM];
__device__ __nv_bfloat16 g_hs_hi[(size_t)NSLOT * H_DIM];
__device__ __nv_bfloat16 g_hs_lo[(size_t)NSLOT * H_DIM];

// ---------------- helpers ----------------
__device__ __forceinline__ uint32_t smem_u32(const void* p) {
    uint32_t a;
    asm("{ .reg .u64 t; cvta.to.shared.u64 t, %1; cvt.u32.u64 %0, t; }" : "=r"(a) : "l"(p));
    return a;
}
__device__ __forceinline__ uint32_t pack_bf16(float lo_elem, float hi_elem) {
    uint32_t r;
    asm("cvt.rn.bf16x2.f32 %0, %1, %2;" : "=r"(r) : "f"(hi_elem), "f"(lo_elem));
    return r;
}
__device__ __forceinline__ float2 unpack_bf16(uint32_t w) {
    float2 r;
    r.x = __uint_as_float(w << 16);
    r.y = __uint_as_float(w & 0xffff0000u);
    return r;
}
__device__ __forceinline__ void mma_bf16(float* d, const uint32_t* a, const uint32_t* b) {
    asm volatile(
        "mma.sync.aligned.m16n8k16.row.col.f32.bf16.bf16.f32 "
        "{%0,%1,%2,%3}, {%4,%5,%6,%7}, {%8,%9}, {%0,%1,%2,%3};"
        : "+f"(d[0]), "+f"(d[1]), "+f"(d[2]), "+f"(d[3])
        : "r"(a[0]), "r"(a[1]), "r"(a[2]), "r"(a[3]), "r"(b[0]), "r"(b[1]));
}
__device__ __forceinline__ void red_add_v2(float* p, float a, float b) {
    asm volatile("red.global.add.v2.f32 [%0], {%1, %2};"
                 :: "l"(p), "f"(a), "f"(b) : "memory");
}
#define LDSM4(r, addr) \
    asm volatile("ldmatrix.sync.aligned.m8n8.x4.shared.b16 {%0,%1,%2,%3}, [%4];" \
        : "=r"((r)[0]), "=r"((r)[1]), "=r"((r)[2]), "=r"((r)[3]) : "r"(addr))
#define LDSM4T(r, addr) \
    asm volatile("ldmatrix.sync.aligned.m8n8.x4.trans.shared.b16 {%0,%1,%2,%3}, [%4];" \
        : "=r"((r)[0]), "=r"((r)[1]), "=r"((r)[2]), "=r"((r)[3]) : "r"(addr))
#define CP16(dst, src) \
    asm volatile("cp.async.cg.shared.global [%0], [%1], 16;" :: "r"(dst), "l"(src))
#define CPCOMMIT() asm volatile("cp.async.commit_group;" ::: "memory")
#define CPWAIT1()  asm volatile("cp.async.wait_group 1;" ::: "memory")

// ---------------- fused prologue: splits + moe-out zero + gating ----------------
// blockIdx.y: 0 = split x (+ zero moe-out), 1 = split W1, 2 = split W2,
//             3 = gating (first 1024 blocks).
// g_counts is zeroed by cudaMemsetAsync BEFORE this launch.
__global__ void prologue_kernel(const float* __restrict__ x,
                                const float* __restrict__ W1,
                                const float* __restrict__ W2,
                                float* __restrict__ out_moe, int n4,
                                const float* __restrict__ noise,
                                const float* __restrict__ Wg, const float* __restrict__ bg,
                                const float* __restrict__ Wn, const float* __restrict__ bn,
                                float* __restrict__ out_clean,
                                float* __restrict__ out_idx,
                                int B)
{
    int which = blockIdx.y;
    if (which < 3) {
        const float* in = (which == 0) ? x : (which == 1) ? W1 : W2;
        __nv_bfloat16* hi = (which == 0) ? g_xs_hi : (which == 1) ? g_w1_hi : g_w2_hi;
        __nv_bfloat16* lo = (which == 0) ? g_xs_lo : (which == 1) ? g_w1_lo : g_w2_lo;

        int i0 = blockIdx.x * (blockDim.x * 2) + threadIdx.x;
        int i1 = i0 + blockDim.x;
        #pragma unroll
        for (int r = 0; r < 2; r++) {
            int i = r ? i1 : i0;
            if (i < n4) {
                float4 v = ((const float4*)in)[i];
                uint32_t h0 = pack_bf16(v.x, v.y), h1 = pack_bf16(v.z, v.w);
                float2 f0 = unpack_bf16(h0), f1 = unpack_bf16(h1);
                uint32_t l0 = pack_bf16(v.x - f0.x, v.y - f0.y);
                uint32_t l1 = pack_bf16(v.z - f1.x, v.w - f1.y);
                ((uint2*)hi)[i] = make_uint2(h0, h1);
                ((uint2*)lo)[i] = make_uint2(l0, l1);
                if (which == 0)
                    ((float4*)out_moe)[i] = make_float4(0.f, 0.f, 0.f, 0.f);
            }
        }
        return;
    }

    // ---- gating slice (exact fp32, one warp per token) ----
    int warp = threadIdx.x >> 5;
    int lane = threadIdx.x & 31;
    int tok  = blockIdx.x * 8 + warp;
    if (blockIdx.x >= (unsigned)((B + 7) / 8) || tok >= B) return;

    const float* xr = x + (size_t)tok * D_DIM;
    float cg[E_NUM] = {}, cn[E_NUM] = {};
    for (int d = lane; d < D_DIM; d += 32) {
        float xv = __ldg(xr + d);
        const float4* wg = (const float4*)(Wg + d * E_NUM);
        const float4* wn = (const float4*)(Wn + d * E_NUM);
        float4 a = wg[0], b = wg[1], c = wn[0], e4 = wn[1];
        cg[0] += xv * a.x;  cg[1] += xv * a.y;  cg[2] += xv * a.z;  cg[3] += xv * a.w;
        cg[4] += xv * b.x;  cg[5] += xv * b.y;  cg[6] += xv * b.z;  cg[7] += xv * b.w;
        cn[0] += xv * c.x;  cn[1] += xv * c.y;  cn[2] += xv * c.z;  cn[3] += xv * c.w;
        cn[4] += xv * e4.x; cn[5] += xv * e4.y; cn[6] += xv * e4.z; cn[7] += xv * e4.w;
    }
    #pragma unroll
    for (int off = 16; off > 0; off >>= 1) {
        #pragma unroll
        for (int e = 0; e < E_NUM; e++) {
            cg[e] += __shfl_xor_sync(0xffffffff, cg[e], off);
            cn[e] += __shfl_xor_sync(0xffffffff, cn[e], off);
        }
    }
    if (lane == 0) {
        float noisy[E_NUM];
        #pragma unroll
        for (int e = 0; e < E_NUM; e++) {
            float clean = cg[e] + bg[e];
            float z = cn[e] + bn[e];
            float sp = (z > 0.0f) ? z + log1pf(expf(-z)) : log1pf(expf(z));
            noisy[e] = clean + noise[(size_t)tok * E_NUM + e] * sp;
            out_clean[(size_t)tok * E_NUM + e] = clean;
        }
        int i0 = 0;
        #pragma unroll
        for (int e = 1; e < E_NUM; e++) if (noisy[e] > noisy[i0]) i0 = e;
        int i1 = (i0 == 0) ? 1 : 0;
        #pragma unroll
        for (int e = 0; e < E_NUM; e++)
            if (e != i0 && noisy[e] > noisy[i1]) i1 = e;

        float v0 = noisy[i0], v1 = noisy[i1];
        float e1 = expf(v1 - v0);
        float w0 = 1.0f / (1.0f + e1);
        float w1 = e1 / (1.0f + e1);

        out_idx[(size_t)tok * 2 + 0] = (float)i0;
        out_idx[(size_t)tok * 2 + 1] = (float)i1;

        int p0 = atomicAdd(&g_counts[i0], 1);
        g_tok [i0 * B_MAX + p0] = tok;
        g_gate[i0 * B_MAX + p0] = w0;
        int p1 = atomicAdd(&g_counts[i1], 1);
        g_tok [i1 * B_MAX + p1] = tok;
        g_gate[i1 * B_MAX + p1] = w1;
    }
}

// ---------------- prefix scan over 8 experts ----------------
__global__ void scan_kernel() {
    if (threadIdx.x == 0) {
        int s = 0;
        for (int e = 0; e < E_NUM; e++) { g_base[e] = s; s += g_counts[e]; }
        g_base[E_NUM] = s;
    }
}

// =====================================================================
// bf16x3 grouped GEMM (R9 config: 2-stage cp.async ring, k-slab 32).
// CTA tile 128x128, 8 warps 2(M)x4(N), warp tile 64x32 (16 acc chains).
// SMEM/stage: A hi/lo 128 rows x 80B; B hi/lo 32 rows x 272B = 37888B.
// ATOMIC=1 (gemm2): epilogue red.add.v2.f32 of gate-scaled rows into
// out[tok] (exactly 2 commutative contributions/element -> deterministic).
// =====================================================================
#define OFF_ALO 10240
#define OFF_BHI 20480
#define OFF_BLO 29184
#define STAGE   37888
#define GEMM_DSM (2 * STAGE)

template<int KDIM, int NDIM, bool GATHER, bool ATOMIC>
__global__ __launch_bounds__(256, 2)
void gemm_bf16_kernel(const __nv_bfloat16* __restrict__ Ahi,
                      const __nv_bfloat16* __restrict__ Alo,
                      const __nv_bfloat16* __restrict__ Whi,
                      const __nv_bfloat16* __restrict__ Wlo,
                      const float* __restrict__ bias,
                      float* __restrict__ Out)
{
    int e   = blockIdx.z;
    int cnt = g_counts[e];
    int m0  = blockIdx.y * 128;
    if (m0 >= cnt) return;
    int n0    = blockIdx.x * 128;
    int gbase = g_base[e];

    extern __shared__ char dsm[];
    uint32_t sb = smem_u32(dsm);
    __shared__ int   s_tok[128];
    __shared__ float s_gate[128];

    int t = threadIdx.x, lane = t & 31, w = t >> 5;
    int wm = (w >> 2) * 64, wn = (w & 3) * 32;
    int g  = lane >> 2,  tt = lane & 3;

    for (int i = t; i < 128; i += 256) {
        int mi = min(m0 + i, cnt - 1);
        s_tok[i] = g_tok[e * B_MAX + mi];
        if (ATOMIC) s_gate[i] = g_gate[e * B_MAX + mi];
    }
    __syncthreads();

    // --- cp.async assignments ---
    int R0 = t >> 2, c4 = t & 3;           // A rows R0, R0+64; 16B chunk c4
    size_t rowA0, rowA1;
    if (GATHER) { rowA0 = (size_t)s_tok[R0]; rowA1 = (size_t)s_tok[R0 + 64]; }
    else {
        rowA0 = (size_t)(gbase + min(m0 + R0,      cnt - 1));
        rowA1 = (size_t)(gbase + min(m0 + R0 + 64, cnt - 1));
    }
    const __nv_bfloat16* a0h = Ahi + rowA0 * KDIM + c4 * 8;
    const __nv_bfloat16* a1h = Ahi + rowA1 * KDIM + c4 * 8;
    const __nv_bfloat16* a0l = Alo + rowA0 * KDIM + c4 * 8;
    const __nv_bfloat16* a1l = Alo + rowA1 * KDIM + c4 * 8;
    uint32_t dA0 = R0 * 80 + c4 * 16;
    uint32_t dA1 = (R0 + 64) * 80 + c4 * 16;

    int Rb = t >> 4, cb = t & 15;          // B rows Rb, Rb+16
    const __nv_bfloat16* b0h = Whi + ((size_t)e * KDIM + Rb)      * NDIM + n0 + cb * 8;
    const __nv_bfloat16* b1h = Whi + ((size_t)e * KDIM + Rb + 16) * NDIM + n0 + cb * 8;
    const __nv_bfloat16* b0l = Wlo + ((size_t)e * KDIM + Rb)      * NDIM + n0 + cb * 8;
    const __nv_bfloat16* b1l = Wlo + ((size_t)e * KDIM + Rb + 16) * NDIM + n0 + cb * 8;
    uint32_t dB0 = Rb * 272 + cb * 16;
    uint32_t dB1 = (Rb + 16) * 272 + cb * 16;

    float acc[4][4][4] = {};
    const int S = KDIM / 32;

#define ISSUE(s_) do { \
        uint32_t base_ = sb + (((s_) & 1) ? STAGE : 0); \
        size_t ka_ = (size_t)(s_) * 32; \
        size_t kb_ = (size_t)(s_) * 32 * NDIM; \
        CP16(base_ + dA0,           a0h + ka_); \
        CP16(base_ + dA1,           a1h + ka_); \
        CP16(base_ + OFF_ALO + dA0, a0l + ka_); \
        CP16(base_ + OFF_ALO + dA1, a1l + ka_); \
        CP16(base_ + OFF_BHI + dB0, b0h + kb_); \
        CP16(base_ + OFF_BHI + dB1, b1h + kb_); \
        CP16(base_ + OFF_BLO + dB0, b0l + kb_); \
        CP16(base_ + OFF_BLO + dB1, b1l + kb_); \
    } while (0)

    ISSUE(0); CPCOMMIT();
    ISSUE(1); CPCOMMIT();

    // ldmatrix per-lane address components
    int Lm = lane & 15, Lh = lane >> 4;
    uint32_t aoff = (uint32_t)(wm + Lm) * 80 + Lh * 16;      // + i*1280 + kh*32
    uint32_t boff = (uint32_t)Lm * 272 + (wn + Lh * 8) * 2;  // + kh*4352 + j2*32

    for (int s = 0; s < S; s++) {
        uint32_t base = sb + ((s & 1) ? STAGE : 0);
        CPWAIT1();
        __syncthreads();
        #pragma unroll
        for (int kh = 0; kh < 2; kh++) {
            uint32_t a[4][4], fbh[4][2], fbl[4][2];
            uint32_t bBh = base + OFF_BHI + boff + kh * 4352;
            #pragma unroll
            for (int j2 = 0; j2 < 2; j2++) {
                uint32_t r[4]; LDSM4T(r, bBh + j2 * 32);
                fbh[2*j2][0] = r[0]; fbh[2*j2][1] = r[1];
                fbh[2*j2+1][0] = r[2]; fbh[2*j2+1][1] = r[3];
            }
            uint32_t bBl = base + OFF_BLO + boff + kh * 4352;
            #pragma unroll
            for (int j2 = 0; j2 < 2; j2++) {
                uint32_t r[4]; LDSM4T(r, bBl + j2 * 32);
                fbl[2*j2][0] = r[0]; fbl[2*j2][1] = r[1];
                fbl[2*j2+1][0] = r[2]; fbl[2*j2+1][1] = r[3];
            }
            uint32_t aA = base + aoff + kh * 32;
            #pragma unroll
            for (int i = 0; i < 4; i++) LDSM4(a[i], aA + i * 1280);
            #pragma unroll
            for (int i = 0; i < 4; i++)
                #pragma unroll
                for (int j = 0; j < 4; j++)
                    mma_bf16(acc[i][j], a[i], fbh[j]);
            #pragma unroll
            for (int i = 0; i < 4; i++)
                #pragma unroll
                for (int j = 0; j < 4; j++)
                    mma_bf16(acc[i][j], a[i], fbl[j]);
            uint32_t aL = base + OFF_ALO + aoff + kh * 32;
            #pragma unroll
            for (int i = 0; i < 4; i++) LDSM4(a[i], aL + i * 1280);
            #pragma unroll
            for (int i = 0; i < 4; i++)
                #pragma unroll
                for (int j = 0; j < 4; j++)
                    mma_bf16(acc[i][j], a[i], fbh[j]);
        }
        __syncthreads();
        if (s + 2 < S) ISSUE(s + 2);
        CPCOMMIT();
    }
#undef ISSUE

    // ---- epilogue ----
    const float* brow = bias + (size_t)e * NDIM + n0;
    #pragma unroll
    for (int i = 0; i < 4; i++) {
        #pragma unroll
        for (int f = 0; f < 2; f++) {
            int rloc = wm + i * 16 + g + f * 8;
            int m = m0 + rloc;
            if (m < cnt) {
                if (ATOMIC) {
                    float gw  = s_gate[rloc];
                    int   tok = s_tok[rloc];
                    float* orow = Out + (size_t)tok * NDIM + n0;
                    #pragma unroll
                    for (int j = 0; j < 4; j++) {
                        int col = wn + j * 8 + tt * 2;
                        red_add_v2(orow + col,
                                   (acc[i][j][f*2+0] + __ldg(brow + col))     * gw,
                                   (acc[i][j][f*2+1] + __ldg(brow + col + 1)) * gw);
                    }
                } else {
                    float* orow = Out + (size_t)(gbase + m) * NDIM + n0;
                    #pragma unroll
                    for (int j = 0; j < 4; j++) {
                        int col = wn + j * 8 + tt * 2;
                        float2 o;
                        o.x = acc[i][j][f*2+0] + __ldg(brow + col);
                        o.y = acc[i][j][f*2+1] + __ldg(brow + col + 1);
                        *(float2*)(orow + col) = o;
                    }
                }
            }
        }
    }
}

// ---------------- LayerNorm + GELU -> bf16 hi/lo split of h ----------------
__global__ void ln_gelu_kernel(const float* __restrict__ ln_g,
                               const float* __restrict__ ln_b)
{
    int r = blockIdx.x;
    int e = 0;
    #pragma unroll
    for (int k = 1; k < E_NUM; k++) if (r >= g_base[k]) e = k;

    const float* row = g_hbuf + (size_t)r * H_DIM;
    int t = threadIdx.x;
    float4 v = *(const float4*)(row + t * 4);
    float s  = v.x + v.y + v.z + v.w;
    float sq = v.x * v.x + v.y * v.y + v.z * v.z + v.w * v.w;

    __shared__ float ssum[8], ssq[8];
    int lane = t & 31, wid = t >> 5;
    #pragma unroll
    for (int off = 16; off > 0; off >>= 1) {
        s  += __shfl_xor_sync(0xffffffff, s,  off);
        sq += __shfl_xor_sync(0xffffffff, sq, off);
    }
    if (lane == 0) { ssum[wid] = s; ssq[wid] = sq; }
    __syncthreads();
    float S = 0.0f, SQ = 0.0f;
    #pragma unroll
    for (int w = 0; w < 8; w++) { S += ssum[w]; SQ += ssq[w]; }

    float mean = S * (1.0f / H_DIM);
    float var  = SQ * (1.0f / H_DIM) - mean * mean;
    float inv  = 1.0f / sqrtf(var + 1e-5f);

    const float4 g4 = *(const float4*)(ln_g + (size_t)e * H_DIM + t * 4);
    const float4 b4 = *(const float4*)(ln_b + (size_t)e * H_DIM + t * 4);

    float u;
    u = (v.x - mean) * inv * g4.x + b4.x; v.x = 0.5f * u * (1.0f + erff(u * 0.7071067811865475f));
    u = (v.y - mean) * inv * g4.y + b4.y; v.y = 0.5f * u * (1.0f + erff(u * 0.7071067811865475f));
    u = (v.z - mean) * inv * g4.z + b4.z; v.z = 0.5f * u * (1.0f + erff(u * 0.7071067811865475f));
    u = (v.w - mean) * inv * g4.w + b4.w; v.w = 0.5f * u * (1.0f + erff(u * 0.7071067811865475f));

    uint32_t h0 = pack_bf16(v.x, v.y), h1 = pack_bf16(v.z, v.w);
    float2 f0 = unpack_bf16(h0), f1 = unpack_bf16(h1);
    uint32_t l0 = pack_bf16(v.x - f0.x, v.y - f0.y);
    uint32_t l1 = pack_bf16(v.z - f1.x, v.w - f1.y);
    ((uint2*)(g_hs_hi + (size_t)r * H_DIM))[t] = make_uint2(h0, h1);
    ((uint2*)(g_hs_lo + (size_t)r * H_DIM))[t] = make_uint2(l0, l1);
}

// ---------------- launch ----------------
extern "C" void kernel_launch(void* const* d_in, const int* in_sizes, int n_in,
                              void* d_out, int out_size)
{
    const float* x     = (const float*)d_in[0];
    const float* noise = (const float*)d_in[1];
    const float* Wg    = (const float*)d_in[2];
    const float* bg    = (const float*)d_in[3];
    const float* Wn    = (const float*)d_in[4];
    const float* bn    = (const float*)d_in[5];
    const float* W1    = (const float*)d_in[6];
    const float* b1    = (const float*)d_in[7];
    const float* lng   = (const float*)d_in[8];
    const float* lnb   = (const float*)d_in[9];
    const float* W2    = (const float*)d_in[10];
    const float* b2    = (const float*)d_in[11];

    float* out = (float*)d_out;
    int B = in_sizes[0] / D_DIM;                      // 8192

    float* out_clean = out + (size_t)B * D_DIM;       // [B, E]
    float* out_idx   = out_clean + (size_t)B * E_NUM; // [B, 2] as float

    __nv_bfloat16 *xs_hi, *xs_lo, *w1_hi, *w1_lo, *w2_hi, *w2_lo, *hs_hi, *hs_lo;
    float *hbuf; int* counts_ptr;
    cudaGetSymbolAddress((void**)&xs_hi, g_xs_hi);
    cudaGetSymbolAddress((void**)&xs_lo, g_xs_lo);
    cudaGetSymbolAddress((void**)&w1_hi, g_w1_hi);
    cudaGetSymbolAddress((void**)&w1_lo, g_w1_lo);
    cudaGetSymbolAddress((void**)&w2_hi, g_w2_hi);
    cudaGetSymbolAddress((void**)&w2_lo, g_w2_lo);
    cudaGetSymbolAddress((void**)&hs_hi, g_hs_hi);
    cudaGetSymbolAddress((void**)&hs_lo, g_hs_lo);
    cudaGetSymbolAddress((void**)&hbuf, g_hbuf);
    cudaGetSymbolAddress((void**)&counts_ptr, g_counts);

    cudaFuncSetAttribute((const void*)gemm_bf16_kernel<D_DIM, H_DIM, true, false>,
                         cudaFuncAttributeMaxDynamicSharedMemorySize, GEMM_DSM);
    cudaFuncSetAttribute((const void*)gemm_bf16_kernel<H_DIM, D_DIM, false, true>,
                         cudaFuncAttributeMaxDynamicSharedMemorySize, GEMM_DSM);

    // zero expert counters (async memset is graph-capturable, no allocation)
    cudaMemsetAsync(counts_ptr, 0, E_NUM * sizeof(int));

    // launch 1: fused splits + moe-out zero + gating (independent slices)
    int n4 = B * D_DIM / 4;                           // == E*D*H/4 == 1572864
    prologue_kernel<<<dim3((n4 + 511) / 512, 4), 256>>>(
        x, W1, W2, out, n4,
        noise, Wg, bg, Wn, bn, out_clean, out_idx, B);

    // launch 2: tiny prefix scan
    scan_kernel<<<1, 32>>>();

    // launch 3: gemm1: h = gather(x) @ W1[e] + b1   (N=1024, K=768)
    gemm_bf16_kernel<D_DIM, H_DIM, true, false>
        <<<dim3(H_DIM / 128, B_MAX / 128, E_NUM), 256, GEMM_DSM>>>(
            xs_hi, xs_lo, w1_hi, w1_lo, b1, hbuf);

    // launch 4: LN + GELU + split h
    ln_gelu_kernel<<<2 * B, 256>>>(lng, lnb);

    // launch 5: gemm2 with fused gate-scale + vector-red combine into out
    gemm_bf16_kernel<H_DIM, D_DIM, false, true>
        <<<dim3(D_DIM / 128, B_MAX / 128, E_NUM), 256, GEMM_DSM>>>(
            hs_hi, hs_lo, w2_hi, w2_lo, b2, out);
}

// round 14
// speedup vs baseline: 1.0009x; 1.0009x over previous
#include <cuda_runtime.h>
#include <cuda_bf16.h>
#include <math.h>
#include <stdint.h>

#define D_DIM 768
#define H_DIM 1024
#define E_NUM 8
#define B_MAX 8192
#define NSLOT (2 * B_MAX)

// ---------------- scratch (device globals; no allocations) ----------------
__device__ int   g_counts[E_NUM];
__device__ int   g_base[E_NUM + 1];
__device__ int   g_tok [E_NUM * B_MAX];
__device__ float g_gate[E_NUM * B_MAX];
__device__ float g_hbuf[(size_t)NSLOT * H_DIM];   // fp32 h (pre-LN)
// pre-split bf16 hi/lo operands
__device__ __nv_bfloat16 g_xs_hi[(size_t)B_MAX * D_DIM];
__device__ __nv_bfloat16 g_xs_lo[(size_t)B_MAX * D_DIM];
__device__ __nv_bfloat16 g_w1_hi[(size_t)E_NUM * D_DIM * H_DIM];
__device__ __nv_bfloat16 g_w1_lo[(size_t)E_NUM * D_DIM * H_DIM];
__device__ __nv_bfloat16 g_w2_hi[(size_t)E_NUM * H_DIM * D_DIM];
__device__ __nv_bfloat16 g_w2_lo[(size_t)E_NUM * H_DIM * D_DIM];
__device__ __nv_bfloat16 g_hs_hi[(size_t)NSLOT * H_DIM];
__device__ __nv_bfloat16 g_hs_lo[(size_t)NSLOT * H_DIM];

// ---------------- helpers ----------------
__device__ __forceinline__ uint32_t smem_u32(const void* p) {
    uint32_t a;
    asm("{ .reg .u64 t; cvta.to.shared.u64 t, %1; cvt.u32.u64 %0, t; }" : "=r"(a) : "l"(p));
    return a;
}
__device__ __forceinline__ uint32_t pack_bf16(float lo_elem, float hi_elem) {
    uint32_t r;
    asm("cvt.rn.bf16x2.f32 %0, %1, %2;" : "=r"(r) : "f"(hi_elem), "f"(lo_elem));
    return r;
}
__device__ __forceinline__ float2 unpack_bf16(uint32_t w) {
    float2 r;
    r.x = __uint_as_float(w << 16);
    r.y = __uint_as_float(w & 0xffff0000u);
    return r;
}
__device__ __forceinline__ void mma_bf16(float* d, const uint32_t* a, const uint32_t* b) {
    asm volatile(
        "mma.sync.aligned.m16n8k16.row.col.f32.bf16.bf16.f32 "
        "{%0,%1,%2,%3}, {%4,%5,%6,%7}, {%8,%9}, {%0,%1,%2,%3};"
        : "+f"(d[0]), "+f"(d[1]), "+f"(d[2]), "+f"(d[3])
        : "r"(a[0]), "r"(a[1]), "r"(a[2]), "r"(a[3]), "r"(b[0]), "r"(b[1]));
}
#define LDSM4(r, addr) \
    asm volatile("ldmatrix.sync.aligned.m8n8.x4.shared.b16 {%0,%1,%2,%3}, [%4];" \
        : "=r"((r)[0]), "=r"((r)[1]), "=r"((r)[2]), "=r"((r)[3]) : "r"(addr))
#define LDSM4T(r, addr) \
    asm volatile("ldmatrix.sync.aligned.m8n8.x4.trans.shared.b16 {%0,%1,%2,%3}, [%4];" \
        : "=r"((r)[0]), "=r"((r)[1]), "=r"((r)[2]), "=r"((r)[3]) : "r"(addr))
#define CP16(dst, src) \
    asm volatile("cp.async.cg.shared.global [%0], [%1], 16;" :: "r"(dst), "l"(src))
#define CPCOMMIT() asm volatile("cp.async.commit_group;" ::: "memory")
#define CPWAIT1()  asm volatile("cp.async.wait_group 1;" ::: "memory")

// ---------------- split_all: x/W1/W2 -> bf16 hi/lo, + zero counters & moe-out ----
__global__ void split_all_kernel(const float* __restrict__ x,
                                 const float* __restrict__ W1,
                                 const float* __restrict__ W2,
                                 float* __restrict__ out_moe, int n4)
{
    int which = blockIdx.y;
    const float* in = (which == 0) ? x : (which == 1) ? W1 : W2;
    __nv_bfloat16* hi = (which == 0) ? g_xs_hi : (which == 1) ? g_w1_hi : g_w2_hi;
    __nv_bfloat16* lo = (which == 0) ? g_xs_lo : (which == 1) ? g_w1_lo : g_w2_lo;

    int i0 = blockIdx.x * (blockDim.x * 2) + threadIdx.x;
    int i1 = i0 + blockDim.x;
    #pragma unroll
    for (int r = 0; r < 2; r++) {
        int i = r ? i1 : i0;
        if (i < n4) {
            float4 v = ((const float4*)in)[i];
            uint32_t h0 = pack_bf16(v.x, v.y), h1 = pack_bf16(v.z, v.w);
            float2 f0 = unpack_bf16(h0), f1 = unpack_bf16(h1);
            uint32_t l0 = pack_bf16(v.x - f0.x, v.y - f0.y);
            uint32_t l1 = pack_bf16(v.z - f1.x, v.w - f1.y);
            ((uint2*)hi)[i] = make_uint2(h0, h1);
            ((uint2*)lo)[i] = make_uint2(l0, l1);
            if (which == 0)
                ((float4*)out_moe)[i] = make_float4(0.f, 0.f, 0.f, 0.f);
        }
    }
    if (which == 0 && blockIdx.x == 0 && threadIdx.x < E_NUM)
        g_counts[threadIdx.x] = 0;
}

// ---------------- gating: one warp per token (exact fp32) ----------------
__global__ void gating_kernel(const float* __restrict__ x,
                              const float* __restrict__ noise,
                              const float* __restrict__ Wg, const float* __restrict__ bg,
                              const float* __restrict__ Wn, const float* __restrict__ bn,
                              float* __restrict__ out_clean,
                              float* __restrict__ out_idx,
                              int B)
{
    int warp = threadIdx.x >> 5;
    int lane = threadIdx.x & 31;
    int tok  = blockIdx.x * 8 + warp;
    if (tok >= B) return;

    const float* xr = x + (size_t)tok * D_DIM;
    float cg[E_NUM] = {}, cn[E_NUM] = {};
    for (int d = lane; d < D_DIM; d += 32) {
        float xv = __ldg(xr + d);
        const float4* wg = (const float4*)(Wg + d * E_NUM);
        const float4* wn = (const float4*)(Wn + d * E_NUM);
        float4 a = wg[0], b = wg[1], c = wn[0], e4 = wn[1];
        cg[0] += xv * a.x;  cg[1] += xv * a.y;  cg[2] += xv * a.z;  cg[3] += xv * a.w;
        cg[4] += xv * b.x;  cg[5] += xv * b.y;  cg[6] += xv * b.z;  cg[7] += xv * b.w;
        cn[0] += xv * c.x;  cn[1] += xv * c.y;  cn[2] += xv * c.z;  cn[3] += xv * c.w;
        cn[4] += xv * e4.x; cn[5] += xv * e4.y; cn[6] += xv * e4.z; cn[7] += xv * e4.w;
    }
    #pragma unroll
    for (int off = 16; off > 0; off >>= 1) {
        #pragma unroll
        for (int e = 0; e < E_NUM; e++) {
            cg[e] += __shfl_xor_sync(0xffffffff, cg[e], off);
            cn[e] += __shfl_xor_sync(0xffffffff, cn[e], off);
        }
    }
    if (lane == 0) {
        float noisy[E_NUM];
        #pragma unroll
        for (int e = 0; e < E_NUM; e++) {
            float clean = cg[e] + bg[e];
            float z = cn[e] + bn[e];
            float sp = (z > 0.0f) ? z + log1pf(expf(-z)) : log1pf(expf(z));
            noisy[e] = clean + noise[(size_t)tok * E_NUM + e] * sp;
            out_clean[(size_t)tok * E_NUM + e] = clean;
        }
        int i0 = 0;
        #pragma unroll
        for (int e = 1; e < E_NUM; e++) if (noisy[e] > noisy[i0]) i0 = e;
        int i1 = (i0 == 0) ? 1 : 0;
        #pragma unroll
        for (int e = 0; e < E_NUM; e++)
            if (e != i0 && noisy[e] > noisy[i1]) i1 = e;

        float v0 = noisy[i0], v1 = noisy[i1];
        float e1 = expf(v1 - v0);
        float w0 = 1.0f / (1.0f + e1);
        float w1 = e1 / (1.0f + e1);

        out_idx[(size_t)tok * 2 + 0] = (float)i0;
        out_idx[(size_t)tok * 2 + 1] = (float)i1;

        int p0 = atomicAdd(&g_counts[i0], 1);
        g_tok [i0 * B_MAX + p0] = tok;
        g_gate[i0 * B_MAX + p0] = w0;
        int p1 = atomicAdd(&g_counts[i1], 1);
        g_tok [i1 * B_MAX + p1] = tok;
        g_gate[i1 * B_MAX + p1] = w1;
    }
}

// ---------------- prefix scan over 8 experts ----------------
__global__ void scan_kernel() {
    if (threadIdx.x == 0) {
        int s = 0;
        for (int e = 0; e < E_NUM; e++) { g_base[e] = s; s += g_counts[e]; }
        g_base[E_NUM] = s;
    }
}

// =====================================================================
// bf16x3 grouped GEMM (champion config: 2-stage cp.async ring, k-slab 32).
// CTA tile 128x128, 8 warps 2(M)x4(N), warp tile 64x32 (16 acc chains).
// SMEM/stage: A hi/lo 128 rows x 80B; B hi/lo 32 rows x 272B = 37888B.
// ATOMIC=1 (gemm2): epilogue atomicAdds gate-scaled rows into out[tok]
// (exactly 2 commutative contributions per element -> deterministic).
// =====================================================================
#define OFF_ALO 10240
#define OFF_BHI 20480
#define OFF_BLO 29184
#define STAGE   37888
#define GEMM_DSM (2 * STAGE)

template<int KDIM, int NDIM, bool GATHER, bool ATOMIC>
__global__ __launch_bounds__(256, 2)
void gemm_bf16_kernel(const __nv_bfloat16* __restrict__ Ahi,
                      const __nv_bfloat16* __restrict__ Alo,
                      const __nv_bfloat16* __restrict__ Whi,
                      const __nv_bfloat16* __restrict__ Wlo,
                      const float* __restrict__ bias,
                      float* __restrict__ Out)
{
    int e   = blockIdx.z;
    int cnt = g_counts[e];
    int m0  = blockIdx.y * 128;
    if (m0 >= cnt) return;
    int n0    = blockIdx.x * 128;
    int gbase = g_base[e];

    extern __shared__ char dsm[];
    uint32_t sb = smem_u32(dsm);
    __shared__ int   s_tok[128];
    __shared__ float s_gate[128];

    int t = threadIdx.x, lane = t & 31, w = t >> 5;
    int wm = (w >> 2) * 64, wn = (w & 3) * 32;
    int g  = lane >> 2,  tt = lane & 3;

    for (int i = t; i < 128; i += 256) {
        int mi = min(m0 + i, cnt - 1);
        s_tok[i] = g_tok[e * B_MAX + mi];
        if (ATOMIC) s_gate[i] = g_gate[e * B_MAX + mi];
    }
    __syncthreads();

    // --- cp.async assignments ---
    int R0 = t >> 2, c4 = t & 3;           // A rows R0, R0+64; 16B chunk c4
    size_t rowA0, rowA1;
    if (GATHER) { rowA0 = (size_t)s_tok[R0]; rowA1 = (size_t)s_tok[R0 + 64]; }
    else {
        rowA0 = (size_t)(gbase + min(m0 + R0,      cnt - 1));
        rowA1 = (size_t)(gbase + min(m0 + R0 + 64, cnt - 1));
    }
    const __nv_bfloat16* a0h = Ahi + rowA0 * KDIM + c4 * 8;
    const __nv_bfloat16* a1h = Ahi + rowA1 * KDIM + c4 * 8;
    const __nv_bfloat16* a0l = Alo + rowA0 * KDIM + c4 * 8;
    const __nv_bfloat16* a1l = Alo + rowA1 * KDIM + c4 * 8;
    uint32_t dA0 = R0 * 80 + c4 * 16;
    uint32_t dA1 = (R0 + 64) * 80 + c4 * 16;

    int Rb = t >> 4, cb = t & 15;          // B rows Rb, Rb+16
    const __nv_bfloat16* b0h = Whi + ((size_t)e * KDIM + Rb)      * NDIM + n0 + cb * 8;
    const __nv_bfloat16* b1h = Whi + ((size_t)e * KDIM + Rb + 16) * NDIM + n0 + cb * 8;
    const __nv_bfloat16* b0l = Wlo + ((size_t)e * KDIM + Rb)      * NDIM + n0 + cb * 8;
    const __nv_bfloat16* b1l = Wlo + ((size_t)e * KDIM + Rb + 16) * NDIM + n0 + cb * 8;
    uint32_t dB0 = Rb * 272 + cb * 16;
    uint32_t dB1 = (Rb + 16) * 272 + cb * 16;

    float acc[4][4][4] = {};
    const int S = KDIM / 32;

#define ISSUE(s_) do { \
        uint32_t base_ = sb + (((s_) & 1) ? STAGE : 0); \
        size_t ka_ = (size_t)(s_) * 32; \
        size_t kb_ = (size_t)(s_) * 32 * NDIM; \
        CP16(base_ + dA0,           a0h + ka_); \
        CP16(base_ + dA1,           a1h + ka_); \
        CP16(base_ + OFF_ALO + dA0, a0l + ka_); \
        CP16(base_ + OFF_ALO + dA1, a1l + ka_); \
        CP16(base_ + OFF_BHI + dB0, b0h + kb_); \
        CP16(base_ + OFF_BHI + dB1, b1h + kb_); \
        CP16(base_ + OFF_BLO + dB0, b0l + kb_); \
        CP16(base_ + OFF_BLO + dB1, b1l + kb_); \
    } while (0)

    ISSUE(0); CPCOMMIT();
    ISSUE(1); CPCOMMIT();

    // ldmatrix per-lane address components
    int Lm = lane & 15, Lh = lane >> 4;
    uint32_t aoff = (uint32_t)(wm + Lm) * 80 + Lh * 16;      // + i*1280 + kh*32
    uint32_t boff = (uint32_t)Lm * 272 + (wn + Lh * 8) * 2;  // + kh*4352 + j2*32

    for (int s = 0; s < S; s++) {
        uint32_t base = sb + ((s & 1) ? STAGE : 0);
        CPWAIT1();
        __syncthreads();
        #pragma unroll
        for (int kh = 0; kh < 2; kh++) {
            uint32_t a[4][4], fbh[4][2], fbl[4][2];
            uint32_t bBh = base + OFF_BHI + boff + kh * 4352;
            #pragma unroll
            for (int j2 = 0; j2 < 2; j2++) {
                uint32_t r[4]; LDSM4T(r, bBh + j2 * 32);
                fbh[2*j2][0] = r[0]; fbh[2*j2][1] = r[1];
                fbh[2*j2+1][0] = r[2]; fbh[2*j2+1][1] = r[3];
            }
            uint32_t bBl = base + OFF_BLO + boff + kh * 4352;
            #pragma unroll
            for (int j2 = 0; j2 < 2; j2++) {
                uint32_t r[4]; LDSM4T(r, bBl + j2 * 32);
                fbl[2*j2][0] = r[0]; fbl[2*j2][1] = r[1];
                fbl[2*j2+1][0] = r[2]; fbl[2*j2+1][1] = r[3];
            }
            uint32_t aA = base + aoff + kh * 32;
            #pragma unroll
            for (int i = 0; i < 4; i++) LDSM4(a[i], aA + i * 1280);
            #pragma unroll
            for (int i = 0; i < 4; i++)
                #pragma unroll
                for (int j = 0; j < 4; j++)
                    mma_bf16(acc[i][j], a[i], fbh[j]);
            #pragma unroll
            for (int i = 0; i < 4; i++)
                #pragma unroll
                for (int j = 0; j < 4; j++)
                    mma_bf16(acc[i][j], a[i], fbl[j]);
            uint32_t aL = base + OFF_ALO + aoff + kh * 32;
            #pragma unroll
            for (int i = 0; i < 4; i++) LDSM4(a[i], aL + i * 1280);
            #pragma unroll
            for (int i = 0; i < 4; i++)
                #pragma unroll
                for (int j = 0; j < 4; j++)
                    mma_bf16(acc[i][j], a[i], fbh[j]);
        }
        __syncthreads();
        if (s + 2 < S) ISSUE(s + 2);
        CPCOMMIT();
    }
#undef ISSUE

    // ---- epilogue ----
    const float* brow = bias + (size_t)e * NDIM + n0;
    #pragma unroll
    for (int i = 0; i < 4; i++) {
        #pragma unroll
        for (int f = 0; f < 2; f++) {
            int rloc = wm + i * 16 + g + f * 8;
            int m = m0 + rloc;
            if (m < cnt) {
                if (ATOMIC) {
                    float gw  = s_gate[rloc];
                    int   tok = s_tok[rloc];
                    float* orow = Out + (size_t)tok * NDIM + n0;
                    #pragma unroll
                    for (int j = 0; j < 4; j++) {
                        int col = wn + j * 8 + tt * 2;
                        atomicAdd(orow + col,     (acc[i][j][f*2+0] + __ldg(brow + col))     * gw);
                        atomicAdd(orow + col + 1, (acc[i][j][f*2+1] + __ldg(brow + col + 1)) * gw);
                    }
                } else {
                    float* orow = Out + (size_t)(gbase + m) * NDIM + n0;
                    #pragma unroll
                    for (int j = 0; j < 4; j++) {
                        int col = wn + j * 8 + tt * 2;
                        float2 o;
                        o.x = acc[i][j][f*2+0] + __ldg(brow + col);
                        o.y = acc[i][j][f*2+1] + __ldg(brow + col + 1);
                        *(float2*)(orow + col) = o;
                    }
                }
            }
        }
    }
}

// ---------------- LayerNorm + GELU -> bf16 hi/lo split of h ----------------
__global__ void ln_gelu_kernel(const float* __restrict__ ln_g,
                               const float* __restrict__ ln_b)
{
    int r = blockIdx.x;
    int e = 0;
    #pragma unroll
    for (int k = 1; k < E_NUM; k++) if (r >= g_base[k]) e = k;

    const float* row = g_hbuf + (size_t)r * H_DIM;
    int t = threadIdx.x;
    float4 v = *(const float4*)(row + t * 4);
    float s  = v.x + v.y + v.z + v.w;
    float sq = v.x * v.x + v.y * v.y + v.z * v.z + v.w * v.w;

    __shared__ float ssum[8], ssq[8];
    int lane = t & 31, wid = t >> 5;
    #pragma unroll
    for (int off = 16; off > 0; off >>= 1) {
        s  += __shfl_xor_sync(0xffffffff, s,  off);
        sq += __shfl_xor_sync(0xffffffff, sq, off);
    }
    if (lane == 0) { ssum[wid] = s; ssq[wid] = sq; }
    __syncthreads();
    float S = 0.0f, SQ = 0.0f;
    #pragma unroll
    for (int w = 0; w < 8; w++) { S += ssum[w]; SQ += ssq[w]; }

    float mean = S * (1.0f / H_DIM);
    float var  = SQ * (1.0f / H_DIM) - mean * mean;
    float inv  = 1.0f / sqrtf(var + 1e-5f);

    const float4 g4 = *(const float4*)(ln_g + (size_t)e * H_DIM + t * 4);
    const float4 b4 = *(const float4*)(ln_b + (size_t)e * H_DIM + t * 4);

    float u;
    u = (v.x - mean) * inv * g4.x + b4.x; v.x = 0.5f * u * (1.0f + erff(u * 0.7071067811865475f));
    u = (v.y - mean) * inv * g4.y + b4.y; v.y = 0.5f * u * (1.0f + erff(u * 0.7071067811865475f));
    u = (v.z - mean) * inv * g4.z + b4.z; v.z = 0.5f * u * (1.0f + erff(u * 0.7071067811865475f));
    u = (v.w - mean) * inv * g4.w + b4.w; v.w = 0.5f * u * (1.0f + erff(u * 0.7071067811865475f));

    uint32_t h0 = pack_bf16(v.x, v.y), h1 = pack_bf16(v.z, v.w);
    float2 f0 = unpack_bf16(h0), f1 = unpack_bf16(h1);
    uint32_t l0 = pack_bf16(v.x - f0.x, v.y - f0.y);
    uint32_t l1 = pack_bf16(v.z - f1.x, v.w - f1.y);
    ((uint2*)(g_hs_hi + (size_t)r * H_DIM))[t] = make_uint2(h0, h1);
    ((uint2*)(g_hs_lo + (size_t)r * H_DIM))[t] = make_uint2(l0, l1);
}

// ---------------- launch ----------------
extern "C" void kernel_launch(void* const* d_in, const int* in_sizes, int n_in,
                              void* d_out, int out_size)
{
    const float* x     = (const float*)d_in[0];
    const float* noise = (const float*)d_in[1];
    const float* Wg    = (const float*)d_in[2];
    const float* bg    = (const float*)d_in[3];
    const float* Wn    = (const float*)d_in[4];
    const float* bn    = (const float*)d_in[5];
    const float* W1    = (const float*)d_in[6];
    const float* b1    = (const float*)d_in[7];
    const float* lng   = (const float*)d_in[8];
    const float* lnb   = (const float*)d_in[9];
    const float* W2    = (const float*)d_in[10];
    const float* b2    = (const float*)d_in[11];

    float* out = (float*)d_out;
    int B = in_sizes[0] / D_DIM;                      // 8192

    float* out_clean = out + (size_t)B * D_DIM;       // [B, E]
    float* out_idx   = out_clean + (size_t)B * E_NUM; // [B, 2] as float

    __nv_bfloat16 *xs_hi, *xs_lo, *w1_hi, *w1_lo, *w2_hi, *w2_lo, *hs_hi, *hs_lo;
    float *hbuf;
    cudaGetSymbolAddress((void**)&xs_hi, g_xs_hi);
    cudaGetSymbolAddress((void**)&xs_lo, g_xs_lo);
    cudaGetSymbolAddress((void**)&w1_hi, g_w1_hi);
    cudaGetSymbolAddress((void**)&w1_lo, g_w1_lo);
    cudaGetSymbolAddress((void**)&w2_hi, g_w2_hi);
    cudaGetSymbolAddress((void**)&w2_lo, g_w2_lo);
    cudaGetSymbolAddress((void**)&hs_hi, g_hs_hi);
    cudaGetSymbolAddress((void**)&hs_lo, g_hs_lo);
    cudaGetSymbolAddress((void**)&hbuf, g_hbuf);

    cudaFuncSetAttribute((const void*)gemm_bf16_kernel<D_DIM, H_DIM, true, false>,
                         cudaFuncAttributeMaxDynamicSharedMemorySize, GEMM_DSM);
    cudaFuncSetAttribute((const void*)gemm_bf16_kernel<H_DIM, D_DIM, false, true>,
                         cudaFuncAttributeMaxDynamicSharedMemorySize, GEMM_DSM);

    // launch 1: fused splits + zero (counters + moe-out region)
    int n4 = B * D_DIM / 4;                           // == E*D*H/4 == 1572864
    split_all_kernel<<<dim3((n4 + 511) / 512, 3), 256>>>(x, W1, W2, out, n4);

    // launch 2-3: gating + scan
    gating_kernel<<<(B + 7) / 8, 256>>>(x, noise, Wg, bg, Wn, bn, out_clean, out_idx, B);
    scan_kernel<<<1, 32>>>();

    // launch 4: gemm1: h = gather(x) @ W1[e] + b1   (N=1024, K=768)
    gemm_bf16_kernel<D_DIM, H_DIM, true, false>
        <<<dim3(H_DIM / 128, B_MAX / 128, E_NUM), 256, GEMM_DSM>>>(
            xs_hi, xs_lo, w1_hi, w1_lo, b1, hbuf);

    // launch 5: LN + GELU + split h
    ln_gelu_kernel<<<2 * B, 256>>>(lng, lnb);

    // launch 6: gemm2 with fused gate-scale + atomic combine into out
    gemm_bf16_kernel<H_DIM, D_DIM, false, true>
        <<<dim3(D_DIM / 128, B_MAX / 128, E_NUM), 256, GEMM_DSM>>>(
            hs_hi, hs_lo, w2_hi, w2_lo, b2, out);
}

// round 15
// speedup vs baseline: 1.0153x; 1.0144x over previous
#include <cuda_runtime.h>
#include <cuda_bf16.h>
#include <math.h>
#include <stdint.h>

#define D_DIM 768
#define H_DIM 1024
#define E_NUM 8
#define B_MAX 8192
#define NSLOT (2 * B_MAX)

// ---------------- scratch (device globals; no allocations) ----------------
__device__ int   g_counts[E_NUM];
__device__ int   g_base[E_NUM + 1];
__device__ int   g_tok [E_NUM * B_MAX];
__device__ float g_gate[E_NUM * B_MAX];
__device__ float g_hbuf[(size_t)NSLOT * H_DIM];   // fp32 h (pre-LN)
// pre-split bf16 hi/lo operands
__device__ __nv_bfloat16 g_xs_hi[(size_t)B_MAX * D_DIM];
__device__ __nv_bfloat16 g_xs_lo[(size_t)B_MAX * D_DIM];
__device__ __nv_bfloat16 g_w1_hi[(size_t)E_NUM * D_DIM * H_DIM];
__device__ __nv_bfloat16 g_w1_lo[(size_t)E_NUM * D_DIM * H_DIM];
__device__ __nv_bfloat16 g_w2_hi[(size_t)E_NUM * H_DIM * D_DIM];
__device__ __nv_bfloat16 g_w2_lo[(size_t)E_NUM * H_DIM * D_DIM];
__device__ __nv_bfloat16 g_hs_hi[(size_t)NSLOT * H_DIM];
__device__ __nv_bfloat16 g_hs_lo[(size_t)NSLOT * H_DIM];

// ---------------- helpers ----------------
__device__ __forceinline__ uint32_t smem_u32(const void* p) {
    uint32_t a;
    asm("{ .reg .u64 t; cvta.to.shared.u64 t, %1; cvt.u32.u64 %0, t; }" : "=r"(a) : "l"(p));
    return a;
}
__device__ __forceinline__ uint32_t pack_bf16(float lo_elem, float hi_elem) {
    uint32_t r;
    asm("cvt.rn.bf16x2.f32 %0, %1, %2;" : "=r"(r) : "f"(hi_elem), "f"(lo_elem));
    return r;
}
__device__ __forceinline__ float2 unpack_bf16(uint32_t w) {
    float2 r;
    r.x = __uint_as_float(w << 16);
    r.y = __uint_as_float(w & 0xffff0000u);
    return r;
}
__device__ __forceinline__ void mma_bf16(float* d, const uint32_t* a, const uint32_t* b) {
    asm volatile(
        "mma.sync.aligned.m16n8k16.row.col.f32.bf16.bf16.f32 "
        "{%0,%1,%2,%3}, {%4,%5,%6,%7}, {%8,%9}, {%0,%1,%2,%3};"
        : "+f"(d[0]), "+f"(d[1]), "+f"(d[2]), "+f"(d[3])
        : "r"(a[0]), "r"(a[1]), "r"(a[2]), "r"(a[3]), "r"(b[0]), "r"(b[1]));
}
#define LDSM4(r, addr) \
    asm volatile("ldmatrix.sync.aligned.m8n8.x4.shared.b16 {%0,%1,%2,%3}, [%4];" \
        : "=r"((r)[0]), "=r"((r)[1]), "=r"((r)[2]), "=r"((r)[3]) : "r"(addr))
#define LDSM4T(r, addr) \
    asm volatile("ldmatrix.sync.aligned.m8n8.x4.trans.shared.b16 {%0,%1,%2,%3}, [%4];" \
        : "=r"((r)[0]), "=r"((r)[1]), "=r"((r)[2]), "=r"((r)[3]) : "r"(addr))
#define CP16(dst, src) \
    asm volatile("cp.async.cg.shared.global [%0], [%1], 16;" :: "r"(dst), "l"(src))
#define CPCOMMIT() asm volatile("cp.async.commit_group;" ::: "memory")
#define CPWAIT1()  asm volatile("cp.async.wait_group 1;" ::: "memory")

// ---------------- split_all: x/W1/W2 -> bf16 hi/lo, + zero counters & moe-out ----
__global__ void split_all_kernel(const float* __restrict__ x,
                                 const float* __restrict__ W1,
                                 const float* __restrict__ W2,
                                 float* __restrict__ out_moe, int n4)
{
    int which = blockIdx.y;
    const float* in = (which == 0) ? x : (which == 1) ? W1 : W2;
    __nv_bfloat16* hi = (which == 0) ? g_xs_hi : (which == 1) ? g_w1_hi : g_w2_hi;
    __nv_bfloat16* lo = (which == 0) ? g_xs_lo : (which == 1) ? g_w1_lo : g_w2_lo;

    int i0 = blockIdx.x * (blockDim.x * 2) + threadIdx.x;
    int i1 = i0 + blockDim.x;
    #pragma unroll
    for (int r = 0; r < 2; r++) {
        int i = r ? i1 : i0;
        if (i < n4) {
            float4 v = ((const float4*)in)[i];
            uint32_t h0 = pack_bf16(v.x, v.y), h1 = pack_bf16(v.z, v.w);
            float2 f0 = unpack_bf16(h0), f1 = unpack_bf16(h1);
            uint32_t l0 = pack_bf16(v.x - f0.x, v.y - f0.y);
            uint32_t l1 = pack_bf16(v.z - f1.x, v.w - f1.y);
            ((uint2*)hi)[i] = make_uint2(h0, h1);
            ((uint2*)lo)[i] = make_uint2(l0, l1);
            if (which == 0)
                ((float4*)out_moe)[i] = make_float4(0.f, 0.f, 0.f, 0.f);
        }
    }
    if (which == 0 && blockIdx.x == 0 && threadIdx.x < E_NUM)
        g_counts[threadIdx.x] = 0;
}

// ---------------- gating: one warp per token (exact fp32) ----------------
__global__ void gating_kernel(const float* __restrict__ x,
                              const float* __restrict__ noise,
                              const float* __restrict__ Wg, const float* __restrict__ bg,
                              const float* __restrict__ Wn, const float* __restrict__ bn,
                              float* __restrict__ out_clean,
                              float* __restrict__ out_idx,
                              int B)
{
    int warp = threadIdx.x >> 5;
    int lane = threadIdx.x & 31;
    int tok  = blockIdx.x * 8 + warp;
    if (tok >= B) return;

    const float* xr = x + (size_t)tok * D_DIM;
    float cg[E_NUM] = {}, cn[E_NUM] = {};
    for (int d = lane; d < D_DIM; d += 32) {
        float xv = __ldg(xr + d);
        const float4* wg = (const float4*)(Wg + d * E_NUM);
        const float4* wn = (const float4*)(Wn + d * E_NUM);
        float4 a = wg[0], b = wg[1], c = wn[0], e4 = wn[1];
        cg[0] += xv * a.x;  cg[1] += xv * a.y;  cg[2] += xv * a.z;  cg[3] += xv * a.w;
        cg[4] += xv * b.x;  cg[5] += xv * b.y;  cg[6] += xv * b.z;  cg[7] += xv * b.w;
        cn[0] += xv * c.x;  cn[1] += xv * c.y;  cn[2] += xv * c.z;  cn[3] += xv * c.w;
        cn[4] += xv * e4.x; cn[5] += xv * e4.y; cn[6] += xv * e4.z; cn[7] += xv * e4.w;
    }
    #pragma unroll
    for (int off = 16; off > 0; off >>= 1) {
        #pragma unroll
        for (int e = 0; e < E_NUM; e++) {
            cg[e] += __shfl_xor_sync(0xffffffff, cg[e], off);
            cn[e] += __shfl_xor_sync(0xffffffff, cn[e], off);
        }
    }
    if (lane == 0) {
        float noisy[E_NUM];
        #pragma unroll
        for (int e = 0; e < E_NUM; e++) {
            float clean = cg[e] + bg[e];
            float z = cn[e] + bn[e];
            float sp = (z > 0.0f) ? z + log1pf(expf(-z)) : log1pf(expf(z));
            noisy[e] = clean + noise[(size_t)tok * E_NUM + e] * sp;
            out_clean[(size_t)tok * E_NUM + e] = clean;
        }
        int i0 = 0;
        #pragma unroll
        for (int e = 1; e < E_NUM; e++) if (noisy[e] > noisy[i0]) i0 = e;
        int i1 = (i0 == 0) ? 1 : 0;
        #pragma unroll
        for (int e = 0; e < E_NUM; e++)
            if (e != i0 && noisy[e] > noisy[i1]) i1 = e;

        float v0 = noisy[i0], v1 = noisy[i1];
        float e1 = expf(v1 - v0);
        float w0 = 1.0f / (1.0f + e1);
        float w1 = e1 / (1.0f + e1);

        out_idx[(size_t)tok * 2 + 0] = (float)i0;
        out_idx[(size_t)tok * 2 + 1] = (float)i1;

        int p0 = atomicAdd(&g_counts[i0], 1);
        g_tok [i0 * B_MAX + p0] = tok;
        g_gate[i0 * B_MAX + p0] = w0;
        int p1 = atomicAdd(&g_counts[i1], 1);
        g_tok [i1 * B_MAX + p1] = tok;
        g_gate[i1 * B_MAX + p1] = w1;
    }
}

// ---------------- prefix scan over 8 experts ----------------
__global__ void scan_kernel() {
    if (threadIdx.x == 0) {
        int s = 0;
        for (int e = 0; e < E_NUM; e++) { g_base[e] = s; s += g_counts[e]; }
        g_base[E_NUM] = s;
    }
}

// =====================================================================
// bf16x3 grouped GEMM (champion config: 2-stage cp.async ring, k-slab 32).
// CTA tile 128x128, 8 warps 2(M)x4(N), warp tile 64x32 (16 acc chains).
// SMEM/stage: A hi/lo 128 rows x 80B; B hi/lo 32 rows x 272B = 37888B.
// ATOMIC=1 (gemm2): epilogue atomicAdds gate-scaled rows into out[tok]
// (exactly 2 commutative contributions per element -> deterministic).
// =====================================================================
#define OFF_ALO 10240
#define OFF_BHI 20480
#define OFF_BLO 29184
#define STAGE   37888
#define GEMM_DSM (2 * STAGE)

template<int KDIM, int NDIM, bool GATHER, bool ATOMIC>
__global__ __launch_bounds__(256, 2)
void gemm_bf16_kernel(const __nv_bfloat16* __restrict__ Ahi,
                      const __nv_bfloat16* __restrict__ Alo,
                      const __nv_bfloat16* __restrict__ Whi,
                      const __nv_bfloat16* __restrict__ Wlo,
                      const float* __restrict__ bias,
                      float* __restrict__ Out)
{
    int e   = blockIdx.z;
    int cnt = g_counts[e];
    int m0  = blockIdx.y * 128;
    if (m0 >= cnt) return;
    int n0    = blockIdx.x * 128;
    int gbase = g_base[e];

    extern __shared__ char dsm[];
    uint32_t sb = smem_u32(dsm);
    __shared__ int   s_tok[128];
    __shared__ float s_gate[128];

    int t = threadIdx.x, lane = t & 31, w = t >> 5;
    int wm = (w >> 2) * 64, wn = (w & 3) * 32;
    int g  = lane >> 2,  tt = lane & 3;

    for (int i = t; i < 128; i += 256) {
        int mi = min(m0 + i, cnt - 1);
        s_tok[i] = g_tok[e * B_MAX + mi];
        if (ATOMIC) s_gate[i] = g_gate[e * B_MAX + mi];
    }
    __syncthreads();

    // --- cp.async assignments ---
    int R0 = t >> 2, c4 = t & 3;           // A rows R0, R0+64; 16B chunk c4
    size_t rowA0, rowA1;
    if (GATHER) { rowA0 = (size_t)s_tok[R0]; rowA1 = (size_t)s_tok[R0 + 64]; }
    else {
        rowA0 = (size_t)(gbase + min(m0 + R0,      cnt - 1));
        rowA1 = (size_t)(gbase + min(m0 + R0 + 64, cnt - 1));
    }
    const __nv_bfloat16* a0h = Ahi + rowA0 * KDIM + c4 * 8;
    const __nv_bfloat16* a1h = Ahi + rowA1 * KDIM + c4 * 8;
    const __nv_bfloat16* a0l = Alo + rowA0 * KDIM + c4 * 8;
    const __nv_bfloat16* a1l = Alo + rowA1 * KDIM + c4 * 8;
    uint32_t dA0 = R0 * 80 + c4 * 16;
    uint32_t dA1 = (R0 + 64) * 80 + c4 * 16;

    int Rb = t >> 4, cb = t & 15;          // B rows Rb, Rb+16
    const __nv_bfloat16* b0h = Whi + ((size_t)e * KDIM + Rb)      * NDIM + n0 + cb * 8;
    const __nv_bfloat16* b1h = Whi + ((size_t)e * KDIM + Rb + 16) * NDIM + n0 + cb * 8;
    const __nv_bfloat16* b0l = Wlo + ((size_t)e * KDIM + Rb)      * NDIM + n0 + cb * 8;
    const __nv_bfloat16* b1l = Wlo + ((size_t)e * KDIM + Rb + 16) * NDIM + n0 + cb * 8;
    uint32_t dB0 = Rb * 272 + cb * 16;
    uint32_t dB1 = (Rb + 16) * 272 + cb * 16;

    float acc[4][4][4] = {};
    const int S = KDIM / 32;

#define ISSUE(s_) do { \
        uint32_t base_ = sb + (((s_) & 1) ? STAGE : 0); \
        size_t ka_ = (size_t)(s_) * 32; \
        size_t kb_ = (size_t)(s_) * 32 * NDIM; \
        CP16(base_ + dA0,           a0h + ka_); \
        CP16(base_ + dA1,           a1h + ka_); \
        CP16(base_ + OFF_ALO + dA0, a0l + ka_); \
        CP16(base_ + OFF_ALO + dA1, a1l + ka_); \
        CP16(base_ + OFF_BHI + dB0, b0h + kb_); \
        CP16(base_ + OFF_BHI + dB1, b1h + kb_); \
        CP16(base_ + OFF_BLO + dB0, b0l + kb_); \
        CP16(base_ + OFF_BLO + dB1, b1l + kb_); \
    } while (0)

    ISSUE(0); CPCOMMIT();
    ISSUE(1); CPCOMMIT();

    // ldmatrix per-lane address components
    int Lm = lane & 15, Lh = lane >> 4;
    uint32_t aoff = (uint32_t)(wm + Lm) * 80 + Lh * 16;      // + i*1280 + kh*32
    uint32_t boff = (uint32_t)Lm * 272 + (wn + Lh * 8) * 2;  // + kh*4352 + j2*32

    for (int s = 0; s < S; s++) {
        uint32_t base = sb + ((s & 1) ? STAGE : 0);
        CPWAIT1();
        __syncthreads();
        #pragma unroll
        for (int kh = 0; kh < 2; kh++) {
            uint32_t a[4][4], fbh[4][2], fbl[4][2];
            uint32_t bBh = base + OFF_BHI + boff + kh * 4352;
            #pragma unroll
            for (int j2 = 0; j2 < 2; j2++) {
                uint32_t r[4]; LDSM4T(r, bBh + j2 * 32);
                fbh[2*j2][0] = r[0]; fbh[2*j2][1] = r[1];
                fbh[2*j2+1][0] = r[2]; fbh[2*j2+1][1] = r[3];
            }
            uint32_t bBl = base + OFF_BLO + boff + kh * 4352;
            #pragma unroll
            for (int j2 = 0; j2 < 2; j2++) {
                uint32_t r[4]; LDSM4T(r, bBl + j2 * 32);
                fbl[2*j2][0] = r[0]; fbl[2*j2][1] = r[1];
                fbl[2*j2+1][0] = r[2]; fbl[2*j2+1][1] = r[3];
            }
            uint32_t aA = base + aoff + kh * 32;
            #pragma unroll
            for (int i = 0; i < 4; i++) LDSM4(a[i], aA + i * 1280);
            #pragma unroll
            for (int i = 0; i < 4; i++)
                #pragma unroll
                for (int j = 0; j < 4; j++)
                    mma_bf16(acc[i][j], a[i], fbh[j]);
            #pragma unroll
            for (int i = 0; i < 4; i++)
                #pragma unroll
                for (int j = 0; j < 4; j++)
                    mma_bf16(acc[i][j], a[i], fbl[j]);
            uint32_t aL = base + OFF_ALO + aoff + kh * 32;
            #pragma unroll
            for (int i = 0; i < 4; i++) LDSM4(a[i], aL + i * 1280);
            #pragma unroll
            for (int i = 0; i < 4; i++)
                #pragma unroll
                for (int j = 0; j < 4; j++)
                    mma_bf16(acc[i][j], a[i], fbh[j]);
        }
        __syncthreads();
        if (s + 2 < S) ISSUE(s + 2);
        CPCOMMIT();
    }
#undef ISSUE

    // ---- epilogue ----
    const float* brow = bias + (size_t)e * NDIM + n0;
    #pragma unroll
    for (int i = 0; i < 4; i++) {
        #pragma unroll
        for (int f = 0; f < 2; f++) {
            int rloc = wm + i * 16 + g + f * 8;
            int m = m0 + rloc;
            if (m < cnt) {
                if (ATOMIC) {
                    float gw  = s_gate[rloc];
                    int   tok = s_tok[rloc];
                    float* orow = Out + (size_t)tok * NDIM + n0;
                    #pragma unroll
                    for (int j = 0; j < 4; j++) {
                        int col = wn + j * 8 + tt * 2;
                        float2 bv = *(const float2*)(brow + col);
                        atomicAdd(orow + col,     (acc[i][j][f*2+0] + bv.x) * gw);
                        atomicAdd(orow + col + 1, (acc[i][j][f*2+1] + bv.y) * gw);
                    }
                } else {
                    float* orow = Out + (size_t)(gbase + m) * NDIM + n0;
                    #pragma unroll
                    for (int j = 0; j < 4; j++) {
                        int col = wn + j * 8 + tt * 2;
                        float2 bv = *(const float2*)(brow + col);
                        float2 o;
                        o.x = acc[i][j][f*2+0] + bv.x;
                        o.y = acc[i][j][f*2+1] + bv.y;
                        *(float2*)(orow + col) = o;
                    }
                }
            }
        }
    }
}

// ---------------- LayerNorm + GELU -> bf16 hi/lo split of h ----------------
__global__ void ln_gelu_kernel(const float* __restrict__ ln_g,
                               const float* __restrict__ ln_b)
{
    int r = blockIdx.x;
    int e = 0;
    #pragma unroll
    for (int k = 1; k < E_NUM; k++) if (r >= g_base[k]) e = k;

    const float* row = g_hbuf + (size_t)r * H_DIM;
    int t = threadIdx.x;
    float4 v = *(const float4*)(row + t * 4);
    float s  = v.x + v.y + v.z + v.w;
    float sq = v.x * v.x + v.y * v.y + v.z * v.z + v.w * v.w;

    __shared__ float ssum[8], ssq[8];
    int lane = t & 31, wid = t >> 5;
    #pragma unroll
    for (int off = 16; off > 0; off >>= 1) {
        s  += __shfl_xor_sync(0xffffffff, s,  off);
        sq += __shfl_xor_sync(0xffffffff, sq, off);
    }
    if (lane == 0) { ssum[wid] = s; ssq[wid] = sq; }
    __syncthreads();
    float S = 0.0f, SQ = 0.0f;
    #pragma unroll
    for (int w = 0; w < 8; w++) { S += ssum[w]; SQ += ssq[w]; }

    float mean = S * (1.0f / H_DIM);
    float var  = SQ * (1.0f / H_DIM) - mean * mean;
    float inv  = 1.0f / sqrtf(var + 1e-5f);

    const float4 g4 = *(const float4*)(ln_g + (size_t)e * H_DIM + t * 4);
    const float4 b4 = *(const float4*)(ln_b + (size_t)e * H_DIM + t * 4);

    float u;
    u = (v.x - mean) * inv * g4.x + b4.x; v.x = 0.5f * u * (1.0f + erff(u * 0.7071067811865475f));
    u = (v.y - mean) * inv * g4.y + b4.y; v.y = 0.5f * u * (1.0f + erff(u * 0.7071067811865475f));
    u = (v.z - mean) * inv * g4.z + b4.z; v.z = 0.5f * u * (1.0f + erff(u * 0.7071067811865475f));
    u = (v.w - mean) * inv * g4.w + b4.w; v.w = 0.5f * u * (1.0f + erff(u * 0.7071067811865475f));

    uint32_t h0 = pack_bf16(v.x, v.y), h1 = pack_bf16(v.z, v.w);
    float2 f0 = unpack_bf16(h0), f1 = unpack_bf16(h1);
    uint32_t l0 = pack_bf16(v.x - f0.x, v.y - f0.y);
    uint32_t l1 = pack_bf16(v.z - f1.x, v.w - f1.y);
    ((uint2*)(g_hs_hi + (size_t)r * H_DIM))[t] = make_uint2(h0, h1);
    ((uint2*)(g_hs_lo + (size_t)r * H_DIM))[t] = make_uint2(l0, l1);
}

// ---------------- launch ----------------
extern "C" void kernel_launch(void* const* d_in, const int* in_sizes, int n_in,
                              void* d_out, int out_size)
{
    const float* x     = (const float*)d_in[0];
    const float* noise = (const float*)d_in[1];
    const float* Wg    = (const float*)d_in[2];
    const float* bg    = (const float*)d_in[3];
    const float* Wn    = (const float*)d_in[4];
    const float* bn    = (const float*)d_in[5];
    const float* W1    = (const float*)d_in[6];
    const float* b1    = (const float*)d_in[7];
    const float* lng   = (const float*)d_in[8];
    const float* lnb   = (const float*)d_in[9];
    const float* W2    = (const float*)d_in[10];
    const float* b2    = (const float*)d_in[11];

    float* out = (float*)d_out;
    int B = in_sizes[0] / D_DIM;                      // 8192

    float* out_clean = out + (size_t)B * D_DIM;       // [B, E]
    float* out_idx   = out_clean + (size_t)B * E_NUM; // [B, 2] as float

    __nv_bfloat16 *xs_hi, *xs_lo, *w1_hi, *w1_lo, *w2_hi, *w2_lo, *hs_hi, *hs_lo;
    float *hbuf;
    cudaGetSymbolAddress((void**)&xs_hi, g_xs_hi);
    cudaGetSymbolAddress((void**)&xs_lo, g_xs_lo);
    cudaGetSymbolAddress((void**)&w1_hi, g_w1_hi);
    cudaGetSymbolAddress((void**)&w1_lo, g_w1_lo);
    cudaGetSymbolAddress((void**)&w2_hi, g_w2_hi);
    cudaGetSymbolAddress((void**)&w2_lo, g_w2_lo);
    cudaGetSymbolAddress((void**)&hs_hi, g_hs_hi);
    cudaGetSymbolAddress((void**)&hs_lo, g_hs_lo);
    cudaGetSymbolAddress((void**)&hbuf, g_hbuf);

    cudaFuncSetAttribute((const void*)gemm_bf16_kernel<D_DIM, H_DIM, true, false>,
                         cudaFuncAttributeMaxDynamicSharedMemorySize, GEMM_DSM);
    cudaFuncSetAttribute((const void*)gemm_bf16_kernel<H_DIM, D_DIM, false, true>,
                         cudaFuncAttributeMaxDynamicSharedMemorySize, GEMM_DSM);

    // launch 1: fused splits + zero (counters + moe-out region)
    int n4 = B * D_DIM / 4;                           // == E*D*H/4 == 1572864
    split_all_kernel<<<dim3((n4 + 511) / 512, 3), 256>>>(x, W1, W2, out, n4);

    // launch 2-3: gating + scan
    gating_kernel<<<(B + 7) / 8, 256>>>(x, noise, Wg, bg, Wn, bn, out_clean, out_idx, B);
    scan_kernel<<<1, 32>>>();

    // launch 4: gemm1: h = gather(x) @ W1[e] + b1   (N=1024, K=768)
    gemm_bf16_kernel<D_DIM, H_DIM, true, false>
        <<<dim3(H_DIM / 128, B_MAX / 128, E_NUM), 256, GEMM_DSM>>>(
            xs_hi, xs_lo, w1_hi, w1_lo, b1, hbuf);

    // launch 5: LN + GELU + split h
    ln_gelu_kernel<<<2 * B, 256>>>(lng, lnb);

    // launch 6: gemm2 with fused gate-scale + atomic combine into out
    gemm_bf16_kernel<H_DIM, D_DIM, false, true>
        <<<dim3(D_DIM / 128, B_MAX / 128, E_NUM), 256, GEMM_DSM>>>(
            hs_hi, hs_lo, w2_hi, w2_lo, b2, out);
}